// round 10
// baseline (speedup 1.0000x reference)
#include <cuda_runtime.h>
#include <math_constants.h>

#define BQ 2048
#define NM 50000
#define DD 512
#define KT 16

typedef unsigned long long u64;

// Scratch (static device globals — allocation-free per harness rules)
__device__ float  g_Qn[(size_t)BQ * DD];
__device__ float  g_Mn[(size_t)NM * DD];
__device__ float  g_sims[(size_t)BQ * NM];
__device__ double g_nq[BQ];
__device__ double g_nm[NM];

// ---- packed f32x2 helpers (two independent IEEE fp32 ops per instr) -------
__device__ __forceinline__ u64 pk2(float x, float y) {
    u64 r; asm("mov.b64 %0, {%1, %2};" : "=l"(r) : "f"(x), "f"(y)); return r;
}
__device__ __forceinline__ void upk2(u64 v, float& x, float& y) {
    asm("mov.b64 {%0, %1}, %2;" : "=f"(x), "=f"(y) : "l"(v));
}
__device__ __forceinline__ u64 fma2(u64 a, u64 b, u64 c) {
    u64 d; asm("fma.rn.f32x2 %0, %1, %2, %3;" : "=l"(d) : "l"(a), "l"(b), "l"(c)); return d;
}
__device__ __forceinline__ u64 add2(u64 a, u64 b) {
    u64 d; asm("add.rn.f32x2 %0, %1, %2;" : "=l"(d) : "l"(a), "l"(b)); return d;
}

// ---------------------------------------------------------------------------
// Kernel 1: per-row L2 norm in fp64 (1 warp per row)  [identical to R3]
// ---------------------------------------------------------------------------
__global__ void norm_kernel(const float* __restrict__ X, int rows, int isquery) {
    int row  = blockIdx.x * 8 + (threadIdx.x >> 5);
    int lane = threadIdx.x & 31;
    if (row >= rows) return;
    const float4* p = (const float4*)(X + (size_t)row * DD);
    double s = 0.0;
#pragma unroll
    for (int j = 0; j < 4; j++) {
        float4 v = p[lane + 32 * j];
        s += (double)v.x * v.x + (double)v.y * v.y
           + (double)v.z * v.z + (double)v.w * v.w;
    }
#pragma unroll
    for (int o = 16; o > 0; o >>= 1) s += __shfl_xor_sync(0xffffffffu, s, o);
    if (lane == 0) {
        double n = sqrt(s);
        n = fmax(n, 1e-12);
        if (isquery) g_nq[row] = n; else g_nm[row] = n;
    }
}

// ---------------------------------------------------------------------------
// Kernel 2: normalize with fp64 division, single rounding  [identical to R3]
// ---------------------------------------------------------------------------
__global__ void normalize_kernel(const float* __restrict__ X, int rows, int isquery) {
    int i = blockIdx.x * blockDim.x + threadIdx.x;   // float4 index
    int total = rows * (DD / 4);
    if (i >= total) return;
    int row = i >> 7;                                // / (DD/4)
    double n = isquery ? g_nq[row] : g_nm[row];
    float4 v = ((const float4*)X)[i];
    v.x = (float)((double)v.x / n);
    v.y = (float)((double)v.y / n);
    v.z = (float)((double)v.z / n);
    v.w = (float)((double)v.w / n);
    if (isquery) ((float4*)g_Qn)[i] = v; else ((float4*)g_Mn)[i] = v;
}

// ---------------------------------------------------------------------------
// Kernel 3: GEMM (NT): sims = Qn * Mn^T.
// Numerics bit-identical to R6/R8: fp32 FMA chains within K-chunks of 16
// (same per-accumulator k order, two lanes per FFMA2), Kahan fold of chunk
// partials. 128x128 tile, 512 threads (4 warps/SMSP for latency hiding),
// 4x8 micro-tile (4 rows x 4 column-pairs).
// ---------------------------------------------------------------------------
#define BM  128
#define BN  128
#define BK  16
#define SPAD 132

__global__ __launch_bounds__(512)
void sgemm_kernel(const int* __restrict__ qids, const int* __restrict__ mids) {
    __shared__ float As[BK][SPAD];   // transposed: As[k][row]
    __shared__ float Bs[BK][SPAD];

    int tid = threadIdx.x;
    int tx = tid & 15;       // 0..15 -> 8 cols (4 pairs) each
    int ty = tid >> 4;       // 0..31 -> 4 rows each
    int q0 = blockIdx.y * BM;
    int n0 = blockIdx.x * BN;

    // per-tile loads: 512 float4 per array / 512 threads = 1 each
    int lr = tid >> 2;              // row 0..127
    int lk = (tid & 3) << 2;        // k offset 0,4,8,12

    const u64 NEG1 = pk2(-1.0f, -1.0f);
    const u64 Z    = pk2(0.f, 0.f);

    u64 s2[4][4], c2[4][4];
#pragma unroll
    for (int i = 0; i < 4; i++)
#pragma unroll
        for (int p = 0; p < 4; p++) { s2[i][p] = Z; c2[i][p] = Z; }

    // prefetch tile 0
    float4 pA, pB;
    {
        pA = *(const float4*)(g_Qn + (size_t)(q0 + lr) * DD + lk);
        int nr = n0 + lr;
        pB = make_float4(0.f, 0.f, 0.f, 0.f);
        if (nr < NM) pB = *(const float4*)(g_Mn + (size_t)nr * DD + lk);
    }

    const int NIT = DD / BK;   // 32
    for (int it = 0; it < NIT; it++) {
        __syncthreads();
        As[lk + 0][lr] = pA.x; As[lk + 1][lr] = pA.y;
        As[lk + 2][lr] = pA.z; As[lk + 3][lr] = pA.w;
        Bs[lk + 0][lr] = pB.x; Bs[lk + 1][lr] = pB.y;
        Bs[lk + 2][lr] = pB.z; Bs[lk + 3][lr] = pB.w;
        __syncthreads();

        if (it + 1 < NIT) {
            int kc = (it + 1) * BK;
            pA = *(const float4*)(g_Qn + (size_t)(q0 + lr) * DD + kc + lk);
            int nr = n0 + lr;
            if (nr < NM) pB = *(const float4*)(g_Mn + (size_t)nr * DD + kc + lk);
        }

        u64 accf[4][4];
#pragma unroll
        for (int i = 0; i < 4; i++)
#pragma unroll
            for (int p = 0; p < 4; p++) accf[i][p] = Z;

#pragma unroll
        for (int k = 0; k < BK; k++) {
            float4 a = *(const float4*)&As[k][ty * 4];
            ulonglong2 B01 = *(const ulonglong2*)&Bs[k][tx * 8];
            ulonglong2 B23 = *(const ulonglong2*)&Bs[k][tx * 8 + 4];
            u64 b0 = B01.x, b1 = B01.y, b2 = B23.x, b3 = B23.y;
            float av[4] = {a.x, a.y, a.z, a.w};
#pragma unroll
            for (int i = 0; i < 4; i++) {
                u64 ai = pk2(av[i], av[i]);
                accf[i][0] = fma2(ai, b0, accf[i][0]);
                accf[i][1] = fma2(ai, b1, accf[i][1]);
                accf[i][2] = fma2(ai, b2, accf[i][2]);
                accf[i][3] = fma2(ai, b3, accf[i][3]);
            }
        }
        // Kahan fold of this chunk partial (packed; same roundings per lane)
#pragma unroll
        for (int i = 0; i < 4; i++)
#pragma unroll
            for (int p = 0; p < 4; p++) {
                u64 y = fma2(c2[i][p], NEG1, accf[i][p]);  // accf - c
                u64 t = add2(s2[i][p], y);                 // s + y
                u64 v = fma2(s2[i][p], NEG1, t);           // t - s
                c2[i][p] = fma2(y, NEG1, v);               // (t-s) - y
                s2[i][p] = t;
            }
    }

    // Epilogue: self-id mask + threshold, write sims (-inf for invalid).
    int qid[4];
#pragma unroll
    for (int i = 0; i < 4; i++) qid[i] = qids[q0 + ty * 4 + i];
    int mid[8];
#pragma unroll
    for (int j = 0; j < 8; j++) {
        int n = n0 + tx * 8 + j;
        mid[j] = (n < NM) ? mids[n] : -1;
    }
#pragma unroll
    for (int i = 0; i < 4; i++) {
        size_t rb = (size_t)(q0 + ty * 4 + i) * NM;
#pragma unroll
        for (int jg = 0; jg < 2; jg++) {
            float4 o;
            float* op = &o.x;
#pragma unroll
            for (int p = 0; p < 2; p++) {
                int pp = jg * 2 + p;
                u64 r = fma2(c2[i][pp], NEG1, s2[i][pp]);   // s - c (Kahan)
                float lo, hi;
                upk2(r, lo, hi);
                float vlo = lo, vhi = hi;
                if (qid[i] == mid[pp * 2 + 0] || vlo < 0.f) vlo = -CUDART_INF_F;
                if (qid[i] == mid[pp * 2 + 1] || vhi < 0.f) vhi = -CUDART_INF_F;
                op[p * 2 + 0] = vlo;
                op[p * 2 + 1] = vhi;
            }
            int nc = n0 + tx * 8 + jg * 4;
            if (nc + 3 < NM) {
                *(float4*)(g_sims + rb + nc) = o;
            } else {
#pragma unroll
                for (int j = 0; j < 4; j++)
                    if (nc + j < NM) g_sims[rb + nc + j] = op[j];
            }
        }
    }
}

// ---------------------------------------------------------------------------
// Kernel 4: per-row top-16 + gather + output writes. 1 CTA per query row.
// Tie-break: equal values -> lower memory index first.  [identical to R3]
// ---------------------------------------------------------------------------
__global__ __launch_bounds__(256)
void topk_kernel(const float* __restrict__ Mraw, const int* __restrict__ mids,
                 float* __restrict__ out) {
    int b = blockIdx.x;
    int tid = threadIdx.x;
    const float* row = g_sims + (size_t)b * NM;

    float v[KT];
    int   id[KT];
#pragma unroll
    for (int s = 0; s < KT; s++) { v[s] = -CUDART_INF_F; id[s] = 0x7fffffff; }

    for (int i = tid * 4; i < NM; i += 1024) {
        float4 x = *(const float4*)(row + i);
        float xs[4] = {x.x, x.y, x.z, x.w};
#pragma unroll
        for (int j = 0; j < 4; j++) {
            float nv = xs[j];
            if (nv > v[0]) {
                v[0] = nv; id[0] = i + j;
#pragma unroll
                for (int s = 0; s < KT - 1; s++) {
                    if (v[s] > v[s + 1]) {
                        float tv = v[s]; v[s] = v[s + 1]; v[s + 1] = tv;
                        int ti = id[s]; id[s] = id[s + 1]; id[s + 1] = ti;
                    }
                }
            }
        }
    }

    __shared__ float sval[4096];
    __shared__ int   sidx[4096];
    __shared__ float rv[256];
    __shared__ int   ri[256];
    __shared__ int   rp[256];
    __shared__ float wv[KT];
    __shared__ int   wi[KT];

#pragma unroll
    for (int s = 0; s < KT; s++) {
        sval[tid * KT + s] = v[s];
        sidx[tid * KT + s] = id[s];
    }
    __syncthreads();

    for (int r = 0; r < KT; r++) {
        float bm = -CUDART_INF_F; int bi = 0x7fffffff; int bp = 0;
#pragma unroll
        for (int t = 0; t < 16; t++) {
            int p = tid + t * 256;
            float x = sval[p];
            int   xi = sidx[p];
            if (x > bm || (x == bm && xi < bi)) { bm = x; bi = xi; bp = p; }
        }
        rv[tid] = bm; ri[tid] = bi; rp[tid] = bp;
        __syncthreads();
        for (int st = 128; st > 0; st >>= 1) {
            if (tid < st) {
                float xo = rv[tid + st];
                if (xo > rv[tid] || (xo == rv[tid] && ri[tid + st] < ri[tid])) {
                    rv[tid] = xo; ri[tid] = ri[tid + st]; rp[tid] = rp[tid + st];
                }
            }
            __syncthreads();
        }
        if (tid == 0) {
            wv[r] = rv[0];
            wi[r] = ri[0];
            sval[rp[0]] = -CUDART_INF_F;
            sidx[rp[0]] = 0x7fffffff;
        }
        __syncthreads();
    }

    const size_t OFF_SIMS = (size_t)BQ * KT * DD;
    const size_t OFF_MASK = OFF_SIMS + (size_t)BQ * KT;
    const size_t OFF_IDS  = OFF_MASK + (size_t)BQ * KT;

    if (tid < KT) {
        float val = wv[tid];
        bool valid = (val > -CUDART_INF_F);
        out[OFF_SIMS + (size_t)b * KT + tid] = val;
        out[OFF_MASK + (size_t)b * KT + tid] = valid ? 1.0f : 0.0f;
        out[OFF_IDS  + (size_t)b * KT + tid] = (float)mids[wi[tid]];
    }
    __syncthreads();

    for (int e = tid; e < KT * (DD / 4); e += 256) {
        int kk = e >> 7;
        int c4 = e & 127;
        int src = wi[kk];
        ((float4*)out)[((size_t)b * KT + kk) * (DD / 4) + c4] =
            ((const float4*)Mraw)[(size_t)src * (DD / 4) + c4];
    }
}

// ---------------------------------------------------------------------------
extern "C" void kernel_launch(void* const* d_in, const int* in_sizes, int n_in,
                              void* d_out, int out_size) {
    const float* Q    = (const float*)d_in[0];   // [2048, 512] f32
    const int*   qids = (const int*)  d_in[1];   // [2048] i32
    const float* M    = (const float*)d_in[2];   // [50000, 512] f32
    const int*   mids = (const int*)  d_in[3];   // [50000] i32
    float* out = (float*)d_out;

    norm_kernel<<<(NM + 7) / 8, 256>>>(M, NM, 0);
    norm_kernel<<<(BQ + 7) / 8, 256>>>(Q, BQ, 1);

    normalize_kernel<<<(NM * (DD / 4) + 255) / 256, 256>>>(M, NM, 0);
    normalize_kernel<<<(BQ * (DD / 4) + 255) / 256, 256>>>(Q, BQ, 1);

    dim3 grid((NM + BN - 1) / BN, BQ / BM);   // (391, 16)
    sgemm_kernel<<<grid, 512>>>(qids, mids);

    topk_kernel<<<BQ, 256>>>(M, mids, out);
}

// round 11
// speedup vs baseline: 1.0621x; 1.0621x over previous
#include <cuda_runtime.h>
#include <math_constants.h>

#define BQ 2048
#define NM 50000
#define DD 512
#define KT 16

typedef unsigned long long u64;

// Scratch (static device globals — allocation-free per harness rules)
__device__ float  g_Qn[(size_t)BQ * DD];
__device__ float  g_Mn[(size_t)NM * DD];
__device__ float  g_sims[(size_t)BQ * NM];
__device__ double g_nq[BQ];
__device__ double g_nm[NM];

// ---- packed f32x2 helpers (two independent IEEE fp32 ops per instr) -------
__device__ __forceinline__ u64 pk2(float x, float y) {
    u64 r; asm("mov.b64 %0, {%1, %2};" : "=l"(r) : "f"(x), "f"(y)); return r;
}
__device__ __forceinline__ void upk2(u64 v, float& x, float& y) {
    asm("mov.b64 {%0, %1}, %2;" : "=f"(x), "=f"(y) : "l"(v));
}
__device__ __forceinline__ u64 fma2(u64 a, u64 b, u64 c) {
    u64 d; asm("fma.rn.f32x2 %0, %1, %2, %3;" : "=l"(d) : "l"(a), "l"(b), "l"(c)); return d;
}
__device__ __forceinline__ u64 add2(u64 a, u64 b) {
    u64 d; asm("add.rn.f32x2 %0, %1, %2;" : "=l"(d) : "l"(a), "l"(b)); return d;
}

// ---------------------------------------------------------------------------
// Kernel 1: per-row L2 norm in fp64 (1 warp per row)  [identical to R3]
// ---------------------------------------------------------------------------
__global__ void norm_kernel(const float* __restrict__ X, int rows, int isquery) {
    int row  = blockIdx.x * 8 + (threadIdx.x >> 5);
    int lane = threadIdx.x & 31;
    if (row >= rows) return;
    const float4* p = (const float4*)(X + (size_t)row * DD);
    double s = 0.0;
#pragma unroll
    for (int j = 0; j < 4; j++) {
        float4 v = p[lane + 32 * j];
        s += (double)v.x * v.x + (double)v.y * v.y
           + (double)v.z * v.z + (double)v.w * v.w;
    }
#pragma unroll
    for (int o = 16; o > 0; o >>= 1) s += __shfl_xor_sync(0xffffffffu, s, o);
    if (lane == 0) {
        double n = sqrt(s);
        n = fmax(n, 1e-12);
        if (isquery) g_nq[row] = n; else g_nm[row] = n;
    }
}

// ---------------------------------------------------------------------------
// Kernel 2: normalize with fp64 division, single rounding  [identical to R3]
// ---------------------------------------------------------------------------
__global__ void normalize_kernel(const float* __restrict__ X, int rows, int isquery) {
    int i = blockIdx.x * blockDim.x + threadIdx.x;   // float4 index
    int total = rows * (DD / 4);
    if (i >= total) return;
    int row = i >> 7;                                // / (DD/4)
    double n = isquery ? g_nq[row] : g_nm[row];
    float4 v = ((const float4*)X)[i];
    v.x = (float)((double)v.x / n);
    v.y = (float)((double)v.y / n);
    v.z = (float)((double)v.z / n);
    v.w = (float)((double)v.w / n);
    if (isquery) ((float4*)g_Qn)[i] = v; else ((float4*)g_Mn)[i] = v;
}

// ---------------------------------------------------------------------------
// Kernel 3: GEMM (NT): sims = Qn * Mn^T.
// Numerics bit-identical to R6/R8/R9: fp32 FMA chains within K-chunks of 16
// (same per-accumulator k order, two lanes per FFMA2), Kahan fold of chunk
// partials. 128x64 tile, 256 threads, 2 CTAs/SM (<=128 regs), 4x8 micro-tile
// (4 rows x 4 column-pairs), double-buffered smem (1 sync per chunk).
// ---------------------------------------------------------------------------
#define BM  128
#define BN  64
#define BK  16
#define PADA 132
#define PADB 68

__global__ __launch_bounds__(256, 2)
void sgemm_kernel(const int* __restrict__ qids, const int* __restrict__ mids) {
    __shared__ float As[2][BK][PADA];   // transposed: As[s][k][row]
    __shared__ float Bs[2][BK][PADB];

    int tid = threadIdx.x;
    int tx = tid & 7;        // 0..7  -> 8 cols (4 pairs) each
    int ty = tid >> 3;       // 0..31 -> 4 rows each
    int q0 = blockIdx.y * BM;
    int n0 = blockIdx.x * BN;

    // per-chunk loads: A 512 f4 -> 2/thread; B 256 f4 -> 1/thread
    int lr = tid >> 2;              // 0..63
    int lk = (tid & 3) << 2;        // k offset 0,4,8,12

    const u64 NEG1 = pk2(-1.0f, -1.0f);
    const u64 Z    = pk2(0.f, 0.f);

    u64 s2[4][4], c2[4][4];
#pragma unroll
    for (int i = 0; i < 4; i++)
#pragma unroll
        for (int p = 0; p < 4; p++) { s2[i][p] = Z; c2[i][p] = Z; }

    // addresses
    const float* aptr0 = g_Qn + (size_t)(q0 + lr) * DD + lk;
    const float* aptr1 = g_Qn + (size_t)(q0 + lr + 64) * DD + lk;
    int nrB = n0 + lr;
    const float* bptr = g_Mn + (size_t)(nrB < NM ? nrB : 0) * DD + lk;
    bool bok = (nrB < NM);

    // prefetch tile 0
    float4 pA0 = *(const float4*)aptr0;
    float4 pA1 = *(const float4*)aptr1;
    float4 pB  = bok ? *(const float4*)bptr : make_float4(0.f, 0.f, 0.f, 0.f);

    // store tile 0 into buffer 0
    As[0][lk + 0][lr] = pA0.x; As[0][lk + 1][lr] = pA0.y;
    As[0][lk + 2][lr] = pA0.z; As[0][lk + 3][lr] = pA0.w;
    As[0][lk + 0][lr + 64] = pA1.x; As[0][lk + 1][lr + 64] = pA1.y;
    As[0][lk + 2][lr + 64] = pA1.z; As[0][lk + 3][lr + 64] = pA1.w;
    Bs[0][lk + 0][lr] = pB.x; Bs[0][lk + 1][lr] = pB.y;
    Bs[0][lk + 2][lr] = pB.z; Bs[0][lk + 3][lr] = pB.w;
    __syncthreads();

    const int NIT = DD / BK;   // 32
#pragma unroll 1
    for (int it = 0; it < NIT; it++) {
        int cur = it & 1;
        // prefetch next tile (LDG latency hidden under compute)
        if (it + 1 < NIT) {
            int kc = (it + 1) * BK;
            pA0 = *(const float4*)(aptr0 + kc);
            pA1 = *(const float4*)(aptr1 + kc);
            if (bok) pB = *(const float4*)(bptr + kc);
        }

        u64 accf[4][4];
#pragma unroll
        for (int i = 0; i < 4; i++)
#pragma unroll
            for (int p = 0; p < 4; p++) accf[i][p] = Z;

#pragma unroll
        for (int k = 0; k < BK; k++) {
            float4 a = *(const float4*)&As[cur][k][ty * 4];
            ulonglong2 B01 = *(const ulonglong2*)&Bs[cur][k][tx * 8];
            ulonglong2 B23 = *(const ulonglong2*)&Bs[cur][k][tx * 8 + 4];
            u64 b0 = B01.x, b1 = B01.y, b2 = B23.x, b3 = B23.y;
            float av[4] = {a.x, a.y, a.z, a.w};
#pragma unroll
            for (int i = 0; i < 4; i++) {
                u64 ai = pk2(av[i], av[i]);
                accf[i][0] = fma2(ai, b0, accf[i][0]);
                accf[i][1] = fma2(ai, b1, accf[i][1]);
                accf[i][2] = fma2(ai, b2, accf[i][2]);
                accf[i][3] = fma2(ai, b3, accf[i][3]);
            }
        }
        // Kahan fold of this chunk partial (packed; same roundings per lane)
#pragma unroll
        for (int i = 0; i < 4; i++)
#pragma unroll
            for (int p = 0; p < 4; p++) {
                u64 y = fma2(c2[i][p], NEG1, accf[i][p]);  // accf - c
                u64 t = add2(s2[i][p], y);                 // s + y
                u64 v = fma2(s2[i][p], NEG1, t);           // t - s
                c2[i][p] = fma2(y, NEG1, v);               // (t-s) - y
                s2[i][p] = t;
            }

        // store next tile into the other buffer
        if (it + 1 < NIT) {
            int nxt = 1 - cur;
            As[nxt][lk + 0][lr] = pA0.x; As[nxt][lk + 1][lr] = pA0.y;
            As[nxt][lk + 2][lr] = pA0.z; As[nxt][lk + 3][lr] = pA0.w;
            As[nxt][lk + 0][lr + 64] = pA1.x; As[nxt][lk + 1][lr + 64] = pA1.y;
            As[nxt][lk + 2][lr + 64] = pA1.z; As[nxt][lk + 3][lr + 64] = pA1.w;
            Bs[nxt][lk + 0][lr] = pB.x; Bs[nxt][lk + 1][lr] = pB.y;
            Bs[nxt][lk + 2][lr] = pB.z; Bs[nxt][lk + 3][lr] = pB.w;
            __syncthreads();
        }
    }

    // Epilogue: self-id mask + threshold, write sims (-inf for invalid).
    int qid[4];
#pragma unroll
    for (int i = 0; i < 4; i++) qid[i] = qids[q0 + ty * 4 + i];
    int mid[8];
#pragma unroll
    for (int j = 0; j < 8; j++) {
        int n = n0 + tx * 8 + j;
        mid[j] = (n < NM) ? mids[n] : -1;
    }
#pragma unroll
    for (int i = 0; i < 4; i++) {
        size_t rb = (size_t)(q0 + ty * 4 + i) * NM;
#pragma unroll
        for (int jg = 0; jg < 2; jg++) {
            float4 o;
            float* op = &o.x;
#pragma unroll
            for (int p = 0; p < 2; p++) {
                int pp = jg * 2 + p;
                u64 r = fma2(c2[i][pp], NEG1, s2[i][pp]);   // s - c (Kahan)
                float lo, hi;
                upk2(r, lo, hi);
                float vlo = lo, vhi = hi;
                if (qid[i] == mid[pp * 2 + 0] || vlo < 0.f) vlo = -CUDART_INF_F;
                if (qid[i] == mid[pp * 2 + 1] || vhi < 0.f) vhi = -CUDART_INF_F;
                op[p * 2 + 0] = vlo;
                op[p * 2 + 1] = vhi;
            }
            int nc = n0 + tx * 8 + jg * 4;
            if (nc + 3 < NM) {
                *(float4*)(g_sims + rb + nc) = o;
            } else {
#pragma unroll
                for (int j = 0; j < 4; j++)
                    if (nc + j < NM) g_sims[rb + nc + j] = op[j];
            }
        }
    }
}

// ---------------------------------------------------------------------------
// Kernel 4: per-row top-16 + gather + output writes. 1 CTA per query row.
// Tie-break: equal values -> lower memory index first.  [identical to R3]
// ---------------------------------------------------------------------------
__global__ __launch_bounds__(256)
void topk_kernel(const float* __restrict__ Mraw, const int* __restrict__ mids,
                 float* __restrict__ out) {
    int b = blockIdx.x;
    int tid = threadIdx.x;
    const float* row = g_sims + (size_t)b * NM;

    float v[KT];
    int   id[KT];
#pragma unroll
    for (int s = 0; s < KT; s++) { v[s] = -CUDART_INF_F; id[s] = 0x7fffffff; }

    for (int i = tid * 4; i < NM; i += 1024) {
        float4 x = *(const float4*)(row + i);
        float xs[4] = {x.x, x.y, x.z, x.w};
#pragma unroll
        for (int j = 0; j < 4; j++) {
            float nv = xs[j];
            if (nv > v[0]) {
                v[0] = nv; id[0] = i + j;
#pragma unroll
                for (int s = 0; s < KT - 1; s++) {
                    if (v[s] > v[s + 1]) {
                        float tv = v[s]; v[s] = v[s + 1]; v[s + 1] = tv;
                        int ti = id[s]; id[s] = id[s + 1]; id[s + 1] = ti;
                    }
                }
            }
        }
    }

    __shared__ float sval[4096];
    __shared__ int   sidx[4096];
    __shared__ float rv[256];
    __shared__ int   ri[256];
    __shared__ int   rp[256];
    __shared__ float wv[KT];
    __shared__ int   wi[KT];

#pragma unroll
    for (int s = 0; s < KT; s++) {
        sval[tid * KT + s] = v[s];
        sidx[tid * KT + s] = id[s];
    }
    __syncthreads();

    for (int r = 0; r < KT; r++) {
        float bm = -CUDART_INF_F; int bi = 0x7fffffff; int bp = 0;
#pragma unroll
        for (int t = 0; t < 16; t++) {
            int p = tid + t * 256;
            float x = sval[p];
            int   xi = sidx[p];
            if (x > bm || (x == bm && xi < bi)) { bm = x; bi = xi; bp = p; }
        }
        rv[tid] = bm; ri[tid] = bi; rp[tid] = bp;
        __syncthreads();
        for (int st = 128; st > 0; st >>= 1) {
            if (tid < st) {
                float xo = rv[tid + st];
                if (xo > rv[tid] || (xo == rv[tid] && ri[tid + st] < ri[tid])) {
                    rv[tid] = xo; ri[tid] = ri[tid + st]; rp[tid] = rp[tid + st];
                }
            }
            __syncthreads();
        }
        if (tid == 0) {
            wv[r] = rv[0];
            wi[r] = ri[0];
            sval[rp[0]] = -CUDART_INF_F;
            sidx[rp[0]] = 0x7fffffff;
        }
        __syncthreads();
    }

    const size_t OFF_SIMS = (size_t)BQ * KT * DD;
    const size_t OFF_MASK = OFF_SIMS + (size_t)BQ * KT;
    const size_t OFF_IDS  = OFF_MASK + (size_t)BQ * KT;

    if (tid < KT) {
        float val = wv[tid];
        bool valid = (val > -CUDART_INF_F);
        out[OFF_SIMS + (size_t)b * KT + tid] = val;
        out[OFF_MASK + (size_t)b * KT + tid] = valid ? 1.0f : 0.0f;
        out[OFF_IDS  + (size_t)b * KT + tid] = (float)mids[wi[tid]];
    }
    __syncthreads();

    for (int e = tid; e < KT * (DD / 4); e += 256) {
        int kk = e >> 7;
        int c4 = e & 127;
        int src = wi[kk];
        ((float4*)out)[((size_t)b * KT + kk) * (DD / 4) + c4] =
            ((const float4*)Mraw)[(size_t)src * (DD / 4) + c4];
    }
}

// ---------------------------------------------------------------------------
extern "C" void kernel_launch(void* const* d_in, const int* in_sizes, int n_in,
                              void* d_out, int out_size) {
    const float* Q    = (const float*)d_in[0];   // [2048, 512] f32
    const int*   qids = (const int*)  d_in[1];   // [2048] i32
    const float* M    = (const float*)d_in[2];   // [50000, 512] f32
    const int*   mids = (const int*)  d_in[3];   // [50000] i32
    float* out = (float*)d_out;

    norm_kernel<<<(NM + 7) / 8, 256>>>(M, NM, 0);
    norm_kernel<<<(BQ + 7) / 8, 256>>>(Q, BQ, 1);

    normalize_kernel<<<(NM * (DD / 4) + 255) / 256, 256>>>(M, NM, 0);
    normalize_kernel<<<(BQ * (DD / 4) + 255) / 256, 256>>>(Q, BQ, 1);

    dim3 grid((NM + BN - 1) / BN, BQ / BM);   // (782, 16)
    sgemm_kernel<<<grid, 256>>>(qids, mids);

    topk_kernel<<<BQ, 256>>>(M, mids, out);
}

// round 16
// speedup vs baseline: 2.9179x; 2.7472x over previous
#include <cuda_runtime.h>
#include <math_constants.h>

#define BQ 2048
#define NM 50000
#define DD 512
#define KT 16
#define NC 32   // candidate count (2x margin over KT)

// Scratch (static device globals — allocation-free per harness rules)
__device__ float  g_Qn[(size_t)BQ * DD];   // fp32 normalized (exact rescore)
__device__ float  g_Mn[(size_t)NM * DD];
__device__ float  g_Qt[(size_t)BQ * DD];   // tf32-rounded (approx GEMM)
__device__ float  g_Mt[(size_t)NM * DD];
__device__ float  g_sims[(size_t)BQ * NM];
__device__ double g_nq[BQ];
__device__ double g_nm[NM];

__device__ __forceinline__ float tf32r(float x) {
    float y; asm("cvt.rna.tf32.f32 %0, %1;" : "=f"(y) : "f"(x)); return y;
}

// m16n8k8 tf32 MMA, fp32 accumulate (row.col)
__device__ __forceinline__ void mma_tf32(float* d, const unsigned* a, const unsigned* b) {
    asm volatile(
        "mma.sync.aligned.m16n8k8.row.col.f32.tf32.tf32.f32 "
        "{%0,%1,%2,%3}, {%4,%5,%6,%7}, {%8,%9}, {%0,%1,%2,%3};"
        : "+f"(d[0]), "+f"(d[1]), "+f"(d[2]), "+f"(d[3])
        : "r"(a[0]), "r"(a[1]), "r"(a[2]), "r"(a[3]), "r"(b[0]), "r"(b[1]));
}

// ---------------------------------------------------------------------------
// Kernel 1: per-row L2 norm in fp64 (1 warp per row)  [identical to R3]
// ---------------------------------------------------------------------------
__global__ void norm_kernel(const float* __restrict__ X, int rows, int isquery) {
    int row  = blockIdx.x * 8 + (threadIdx.x >> 5);
    int lane = threadIdx.x & 31;
    if (row >= rows) return;
    const float4* p = (const float4*)(X + (size_t)row * DD);
    double s = 0.0;
#pragma unroll
    for (int j = 0; j < 4; j++) {
        float4 v = p[lane + 32 * j];
        s += (double)v.x * v.x + (double)v.y * v.y
           + (double)v.z * v.z + (double)v.w * v.w;
    }
#pragma unroll
    for (int o = 16; o > 0; o >>= 1) s += __shfl_xor_sync(0xffffffffu, s, o);
    if (lane == 0) {
        double n = sqrt(s);
        n = fmax(n, 1e-12);
        if (isquery) g_nq[row] = n; else g_nm[row] = n;
    }
}

// ---------------------------------------------------------------------------
// Kernel 2: normalize (fp64 divide, single rounding) -> fp32 + tf32 copies
// ---------------------------------------------------------------------------
__global__ void normalize_kernel(const float* __restrict__ X, int rows, int isquery) {
    int i = blockIdx.x * blockDim.x + threadIdx.x;   // float4 index
    int total = rows * (DD / 4);
    if (i >= total) return;
    int row = i >> 7;                                // / (DD/4)
    double n = isquery ? g_nq[row] : g_nm[row];
    float4 v = ((const float4*)X)[i];
    float4 f, t;
    f.x = (float)((double)v.x / n); t.x = tf32r(f.x);
    f.y = (float)((double)v.y / n); t.y = tf32r(f.y);
    f.z = (float)((double)v.z / n); t.z = tf32r(f.z);
    f.w = (float)((double)v.w / n); t.w = tf32r(f.w);
    if (isquery) { ((float4*)g_Qn)[i] = f; ((float4*)g_Qt)[i] = t; }
    else         { ((float4*)g_Mn)[i] = f; ((float4*)g_Mt)[i] = t; }
}

// ---------------------------------------------------------------------------
// Kernel 3: single-pass TF32 tensor-core GEMM (NT), approximate sims.
// 128x128 tile, 256 threads (8 warps 2x4), warp tile 64x32, m16n8k8.
// Fragments pre-scattered to smem in register order. Epilogue: id-mask only.
// ---------------------------------------------------------------------------
#define BKC 16

__global__ __launch_bounds__(256, 2)
void mma_gemm_kernel(const int* __restrict__ qids, const int* __restrict__ mids) {
    __shared__ float Asm[8][2][32][4];    // 8 KB
    __shared__ float Bsm[16][2][32][2];   // 8 KB

    int tid  = threadIdx.x;
    int lane = tid & 31;
    int wid  = tid >> 5;
    int warp_m = wid >> 2;    // 0..1
    int warp_n = wid & 3;     // 0..3
    int q0 = blockIdx.y * 128;
    int n0 = blockIdx.x * 128;

    int lrow = tid >> 1;              // 0..127
    int lkb  = (tid & 1) * 8;         // 0 or 8

    float acc[4][4][4];
#pragma unroll
    for (int i = 0; i < 4; i++)
#pragma unroll
        for (int j = 0; j < 4; j++)
#pragma unroll
            for (int e = 0; e < 4; e++) acc[i][j][e] = 0.f;

    const float* aptr = g_Qt + (size_t)(q0 + lrow) * DD + lkb;
    int brow = n0 + lrow;
    bool bok = brow < NM;
    const float* bptr = g_Mt + (size_t)(bok ? brow : 0) * DD + lkb;

    int a_tile = lrow >> 4;
    int a_r    = lrow & 15;
    int a_lb   = (a_r & 7) * 4;
    int a_sb   = a_r >> 3;
    int b_tile = lrow >> 3;
    int b_lb   = (lrow & 7) * 4;

    float4 ra[2], rb[2];
#pragma unroll
    for (int e = 0; e < 2; e++) {
        ra[e] = ((const float4*)aptr)[e];
        rb[e] = bok ? ((const float4*)bptr)[e] : make_float4(0.f, 0.f, 0.f, 0.f);
    }

    const int NIT = DD / BKC;   // 32
#pragma unroll 1
    for (int it = 0; it < NIT; it++) {
        __syncthreads();
        const float* raf = (const float*)ra;
        const float* rbf = (const float*)rb;
#pragma unroll
        for (int e = 0; e < 8; e++) {
            int kk = lkb + e;
            int ks = kk >> 3;
            int cc = kk & 7;
            Asm[a_tile][ks][a_lb + (cc & 3)][a_sb + ((cc >> 2) << 1)] = raf[e];
            Bsm[b_tile][ks][b_lb + (cc & 3)][cc >> 2] = rbf[e];
        }
        __syncthreads();

        if (it + 1 < NIT) {
            int kc = (it + 1) * BKC;
#pragma unroll
            for (int e = 0; e < 2; e++) {
                ra[e] = ((const float4*)(aptr + kc))[e];
                if (bok) rb[e] = ((const float4*)(bptr + kc))[e];
            }
        }

#pragma unroll
        for (int ks = 0; ks < 2; ks++) {
            unsigned bf[4][2];
#pragma unroll
            for (int j = 0; j < 4; j++) {
                float2 bv = *(const float2*)&Bsm[warp_n * 4 + j][ks][lane][0];
                bf[j][0] = __float_as_uint(bv.x);
                bf[j][1] = __float_as_uint(bv.y);
            }
#pragma unroll
            for (int i = 0; i < 4; i++) {
                float4 av = *(const float4*)&Asm[warp_m * 4 + i][ks][lane][0];
                unsigned af[4] = {__float_as_uint(av.x), __float_as_uint(av.y),
                                  __float_as_uint(av.z), __float_as_uint(av.w)};
#pragma unroll
                for (int j = 0; j < 4; j++)
                    mma_tf32(acc[i][j], af, bf[j]);
            }
        }
    }

    // Epilogue: self-id mask only (threshold handled at exact rescore).
    int gr = lane >> 2;
    int gc = (lane & 3) * 2;
#pragma unroll
    for (int i = 0; i < 4; i++) {
        int row0 = q0 + warp_m * 64 + i * 16 + gr;
        int qid0 = qids[row0];
        int qid1 = qids[row0 + 8];
        size_t rb0 = (size_t)row0 * NM;
        size_t rb1 = (size_t)(row0 + 8) * NM;
#pragma unroll
        for (int j = 0; j < 4; j++) {
            int col = n0 + warp_n * 32 + j * 8 + gc;
            if (col < NM) {
                int m0 = mids[col];
                int m1 = mids[col + 1];
                float d0 = acc[i][j][0], d1 = acc[i][j][1];
                float d2 = acc[i][j][2], d3 = acc[i][j][3];
                if (qid0 == m0) d0 = -CUDART_INF_F;
                if (qid0 == m1) d1 = -CUDART_INF_F;
                if (qid1 == m0) d2 = -CUDART_INF_F;
                if (qid1 == m1) d3 = -CUDART_INF_F;
                *(float2*)(g_sims + rb0 + col) = make_float2(d0, d1);
                *(float2*)(g_sims + rb1 + col) = make_float2(d2, d3);
            }
        }
    }
}

// ---------------------------------------------------------------------------
// Kernel 4: per-row top-32 approx candidates -> rescore in R3's EXACT
// numeric domain (fp32 FMA chunks of 16, fp64 fold, round to fp32) ->
// threshold + top-16 on fp32 values (lower-index tie-break) -> outputs.
// 1 CTA per query row.
// ---------------------------------------------------------------------------
__global__ __launch_bounds__(256)
void topk_kernel(const float* __restrict__ Mraw, const int* __restrict__ mids,
                 float* __restrict__ out) {
    int b = blockIdx.x;
    int tid = threadIdx.x;
    const float* row = g_sims + (size_t)b * NM;

    // Phase 1: thread-local sorted-16 (ascending; v[0]=min) over approx sims
    float v[KT];
    int   id[KT];
#pragma unroll
    for (int s = 0; s < KT; s++) { v[s] = -CUDART_INF_F; id[s] = 0x7fffffff; }

    for (int i = tid * 4; i < NM; i += 1024) {
        float4 x = *(const float4*)(row + i);
        float xs[4] = {x.x, x.y, x.z, x.w};
#pragma unroll
        for (int j = 0; j < 4; j++) {
            float nv = xs[j];
            if (nv > v[0]) {
                v[0] = nv; id[0] = i + j;
#pragma unroll
                for (int s = 0; s < KT - 1; s++) {
                    if (v[s] > v[s + 1]) {
                        float tv = v[s]; v[s] = v[s + 1]; v[s + 1] = tv;
                        int ti = id[s]; id[s] = id[s + 1]; id[s + 1] = ti;
                    }
                }
            }
        }
    }

    __shared__ float  sval[4096];
    __shared__ int    sidx[4096];
    __shared__ float  rv[256];
    __shared__ int    ri[256];
    __shared__ int    rp[256];
    __shared__ int    cand[NC];
    __shared__ float  rsf[NC];
    __shared__ float  wv[KT];
    __shared__ int    wi[KT];

#pragma unroll
    for (int s = 0; s < KT; s++) {
        sval[tid * KT + s] = v[s];
        sidx[tid * KT + s] = id[s];
    }
    __syncthreads();

    // Phase 2: 32 rounds of block argmax -> candidate set (desc approx)
    for (int r = 0; r < NC; r++) {
        float bm = -CUDART_INF_F; int bi = 0x7fffffff; int bp = 0;
#pragma unroll
        for (int t = 0; t < 16; t++) {
            int p = tid + t * 256;
            float x = sval[p];
            int   xi = sidx[p];
            if (x > bm || (x == bm && xi < bi)) { bm = x; bi = xi; bp = p; }
        }
        rv[tid] = bm; ri[tid] = bi; rp[tid] = bp;
        __syncthreads();
        for (int st = 128; st > 0; st >>= 1) {
            if (tid < st) {
                float xo = rv[tid + st];
                if (xo > rv[tid] || (xo == rv[tid] && ri[tid + st] < ri[tid])) {
                    rv[tid] = xo; ri[tid] = ri[tid + st]; rp[tid] = rp[tid + st];
                }
            }
            __syncthreads();
        }
        if (tid == 0) {
            cand[r] = ri[0];
            sval[rp[0]] = -CUDART_INF_F;
            sidx[rp[0]] = 0x7fffffff;
        }
        __syncthreads();
    }

    // Phase 3: rescore in R3's exact numeric domain — one candidate per lane
    // (warp 0): fp32 FMA chain over k in chunks of 16 (same order as R3's
    // GEMM), chunk partials folded in fp64, rounded once to fp32.
    if (tid < NC) {
        const float* qv = g_Qn + (size_t)b * DD;
        const float* mv = g_Mn + (size_t)cand[tid] * DD;
        double acc = 0.0;
        for (int kc = 0; kc < DD; kc += 16) {
            float a = 0.f;
#pragma unroll
            for (int d = 0; d < 16; d++)
                a = fmaf(qv[kc + d], mv[kc + d], a);
            acc += (double)a;
        }
        float val = (float)acc;
        if (val < 0.f) val = -CUDART_INF_F;   // threshold in fp32 domain
        rsf[tid] = val;
    }
    __syncthreads();

    // Phase 4: top-16 on fp32 values, lower-index tie-break (lax.top_k)
    if (tid == 0) {
        float vals[NC]; int idxs[NC];
#pragma unroll
        for (int c = 0; c < NC; c++) { vals[c] = rsf[c]; idxs[c] = cand[c]; }
        for (int r = 0; r < KT; r++) {
            int best = 0;
            float bv2 = -CUDART_INF_F; int bi2 = 0x7fffffff;
            for (int c = 0; c < NC; c++) {
                if (idxs[c] < 0) continue;
                if (vals[c] > bv2 || (vals[c] == bv2 && idxs[c] < bi2)) {
                    bv2 = vals[c]; bi2 = idxs[c]; best = c;
                }
            }
            wv[r] = vals[best];
            wi[r] = idxs[best];
            idxs[best] = -1;
        }
    }
    __syncthreads();

    // Phase 5: outputs.
    // Layout: retrieved [BQ,KT,DD] | top_sims [BQ,KT] | mask [BQ,KT] | ids [BQ,KT]
    const size_t OFF_SIMS = (size_t)BQ * KT * DD;
    const size_t OFF_MASK = OFF_SIMS + (size_t)BQ * KT;
    const size_t OFF_IDS  = OFF_MASK + (size_t)BQ * KT;

    if (tid < KT) {
        float val = wv[tid];
        bool valid = (val > -CUDART_INF_F);
        out[OFF_SIMS + (size_t)b * KT + tid] = val;
        out[OFF_MASK + (size_t)b * KT + tid] = valid ? 1.0f : 0.0f;
        out[OFF_IDS  + (size_t)b * KT + tid] = (float)mids[wi[tid]];
    }
    __syncthreads();

    for (int e = tid; e < KT * (DD / 4); e += 256) {
        int kk = e >> 7;
        int c4 = e & 127;
        int src = wi[kk];
        ((float4*)out)[((size_t)b * KT + kk) * (DD / 4) + c4] =
            ((const float4*)Mraw)[(size_t)src * (DD / 4) + c4];
    }
}

// ---------------------------------------------------------------------------
extern "C" void kernel_launch(void* const* d_in, const int* in_sizes, int n_in,
                              void* d_out, int out_size) {
    const float* Q    = (const float*)d_in[0];   // [2048, 512] f32
    const int*   qids = (const int*)  d_in[1];   // [2048] i32
    const float* M    = (const float*)d_in[2];   // [50000, 512] f32
    const int*   mids = (const int*)  d_in[3];   // [50000] i32
    float* out = (float*)d_out;

    norm_kernel<<<(NM + 7) / 8, 256>>>(M, NM, 0);
    norm_kernel<<<(BQ + 7) / 8, 256>>>(Q, BQ, 1);

    normalize_kernel<<<(NM * (DD / 4) + 255) / 256, 256>>>(M, NM, 0);
    normalize_kernel<<<(BQ * (DD / 4) + 255) / 256, 256>>>(Q, BQ, 1);

    dim3 grid((NM + 127) / 128, BQ / 128);   // (391, 16)
    mma_gemm_kernel<<<grid, 256>>>(qids, mids);

    topk_kernel<<<BQ, 256>>>(M, mids, out);
}